// round 13
// baseline (speedup 1.0000x reference)
#include <cuda_runtime.h>

#define DIM 16
typedef unsigned long long ull;

#define SGN_BOTH 0x8000000080000000ull
#define SGN_HI   0x8000000000000000ull
#define SGN_LO   0x0000000080000000ull

// ---------- packed f32x2 helpers ----------
__device__ __forceinline__ ull pk2(float lo, float hi){
    ull r; asm("mov.b64 %0, {%1, %2};" : "=l"(r) : "f"(lo), "f"(hi)); return r;
}
__device__ __forceinline__ ull dup2(float v){ return pk2(v, v); }
__device__ __forceinline__ ull fma2(ull a, ull b, ull c){
    ull d; asm("fma.rn.f32x2 %0, %1, %2, %3;" : "=l"(d) : "l"(a), "l"(b), "l"(c)); return d;
}
__device__ __forceinline__ ull mul2(ull a, ull b){
    ull d; asm("mul.rn.f32x2 %0, %1, %2;" : "=l"(d) : "l"(a), "l"(b)); return d;
}
__device__ __forceinline__ ull swp(ull v){
    unsigned lo, hi; asm("mov.b64 {%0, %1}, %2;" : "=r"(lo), "=r"(hi) : "l"(v));
    ull r; asm("mov.b64 %0, {%1, %2};" : "=l"(r) : "r"(hi), "r"(lo)); return r;
}
__device__ __forceinline__ void unpk(ull v, float& lo, float& hi){
    asm("mov.b64 {%0, %1}, %2;" : "=f"(lo), "=f"(hi) : "l"(v));
}

// ---------- scalar complex helpers (prologue + G build) ----------
__device__ __forceinline__ float2 cmul(float2 a, float2 b){
    return make_float2(fmaf(a.x, b.x, -a.y * b.y),
                       fmaf(a.x, b.y,  a.y * b.x));
}
__device__ __forceinline__ float2 cmadd(float2 a, float2 b, float2 acc){
    acc.x = fmaf(a.x, b.x, fmaf(-a.y, b.y, acc.x));
    acc.y = fmaf(a.x, b.y, fmaf( a.y, b.x, acc.y));
    return acc;
}
__device__ __forceinline__ void mm2(const float2* A, const float2* B, float2* C){
    C[0] = cmadd(A[1], B[2], cmul(A[0], B[0]));
    C[1] = cmadd(A[1], B[3], cmul(A[0], B[1]));
    C[2] = cmadd(A[3], B[2], cmul(A[2], B[0]));
    C[3] = cmadd(A[3], B[3], cmul(A[2], B[1]));
}

// build gate G = P * Rz(z)Ry(a)Rx(a) top row from (u,v,ca,sa)
__device__ __forceinline__ void build_G(float u, float v, float ca, float sa,
                                        float2 P00, float2 P01,
                                        float2& G00, float2& G01)
{
    float2 M00 = make_float2(fmaf(ca, v, u), fmaf(-ca, u, v));
    float2 M01 = make_float2(-sa * u, -sa * v);
    float2 M10 = make_float2(-M01.x,  M01.y);
    float2 M11 = make_float2( M00.x, -M00.y);
    G00 = cmadd(P01, M10, cmul(P00, M00));
    G01 = cmadd(P01, M11, cmul(P00, M01));
}

// apply gate (G00,G01) on qubit i to packed state (Rr, Ii). i compile-time.
__device__ __forceinline__ void apply_gate(ull* Rr, ull* Ii, const int i,
                                           float2 G00, float2 G01)
{
    if (i < 3){
        ull pG00x  = dup2(G00.x), pG00y  = dup2(G00.y);
        ull pG01x  = dup2(G01.x), pG01y  = dup2(G01.y);
        ull pnG00y = pG00y ^ SGN_BOTH;
        ull pnG01x = pG01x ^ SGN_BOTH;
        ull pnG01y = pG01y ^ SGN_BOTH;
        const int hs = 4 >> i;
        #pragma unroll
        for (int m = 0; m < 8; m++){
            if (m & hs) continue;
            const int u0 = m, v0 = m + hs;
            ull R0 = Rr[u0], I0 = Ii[u0], R1 = Rr[v0], I1 = Ii[v0];
            Rr[u0] = fma2(pnG01y,I1, fma2(pG01x ,R1, fma2(pnG00y,I0, mul2(pG00x ,R0))));
            Ii[u0] = fma2(pG01x ,I1, fma2(pG01y ,R1, fma2(pG00x ,I0, mul2(pG00y ,R0))));
            Rr[v0] = fma2(pG00y ,I1, fma2(pG00x ,R1, fma2(pnG01y,I0, mul2(pnG01x,R0))));
            Ii[v0] = fma2(pG00x ,I1, fma2(pnG00y,R1, fma2(pnG01x,I0, mul2(pG01y ,R0))));
        }
    } else {
        ull c1  = dup2(G00.x);
        ull c6  = dup2(G01.y);
        ull c2v = dup2(G01.x) ^ SGN_HI;
        ull c3  = dup2(G00.y) ^ SGN_LO;
        ull c4  = c6 ^ SGN_BOTH;
        ull c5  = dup2(G00.y) ^ SGN_HI;
        #pragma unroll
        for (int m = 0; m < 8; m++){
            ull R = Rr[m], I = Ii[m];
            ull Rs = swp(R), Is = swp(I);
            Rr[m] = fma2(c4, Is, fma2(c3, I, fma2(c2v, Rs, mul2(c1, R))));
            Ii[m] = fma2(c6, Rs, fma2(c5, R, fma2(c2v, Is, mul2(c1, I))));
        }
    }
}

__global__ void __launch_bounds__(128) vqc_fused(
    const float4* __restrict__ x, const float* __restrict__ theta,
    const float* __restrict__ lmbd, float4* __restrict__ out, int B)
{
    __shared__ float2 sT[4][4][4];
    __shared__ float2 sP[3][4][2];
    __shared__ float2 sPsi0[DIM];
    __shared__ float  sL[12];

    const int t  = threadIdx.x;
    const int b0 = blockIdx.x * 256 + t;      // elements b0 and b0+128
    const int b1 = b0 + 128;

    // hoisted input loads: overlap DRAM latency with prologue + barriers
    float4 xv0 = make_float4(0.f,0.f,0.f,0.f);
    float4 xv1 = make_float4(0.f,0.f,0.f,0.f);
    if (b0 < B) xv0 = x[b0];
    if (b1 < B) xv1 = x[b1];

    // ---- prologue stage 1 ----
    if (t < 16){
        int l = t >> 2, i = t & 3;
        float t0 = theta[t*3 + 0], t1 = theta[t*3 + 1], t2 = theta[t*3 + 2];
        float cx, sx, cy, sy, cz, sz;
        __sincosf(0.5f*t0, &sx, &cx);
        __sincosf(0.5f*t1, &sy, &cy);
        __sincosf(0.5f*t2, &sz, &cz);
        float2 RX[4] = {{cx,0.f},{0.f,-sx},{0.f,-sx},{cx,0.f}};
        float2 RY[4] = {{cy,0.f},{-sy,0.f},{sy,0.f},{cy,0.f}};
        float2 RZ[4] = {{cz,-sz},{0.f,0.f},{0.f,0.f},{cz,sz}};
        float2 YX[4], M[4];
        mm2(RY, RX, YX);
        mm2(RZ, YX, M);
        #pragma unroll
        for (int e = 0; e < 4; e++) sT[l][i][e] = M[e];
    }
    if (t >= 32 && t < 44) sL[t - 32] = lmbd[t - 32];
    __syncthreads();

    // ---- prologue stage 2 ----
    if (t < 12){
        int l = t >> 2, i = t & 3;
        float2 G0, G1;
        if (l < 2){
            G0 = cmadd(sT[l+1][i][1], sT[3][i][2], cmul(sT[l+1][i][0], sT[3][i][0]));
            G1 = cmadd(sT[l+1][i][1], sT[3][i][3], cmul(sT[l+1][i][0], sT[3][i][1]));
        } else {
            G0 = sT[3][i][0];
            G1 = sT[3][i][1];
        }
        sP[l][i][0] = G0;
        sP[l][i][1] = G1;
    }
    if (t >= 16 && t < 32){
        int s = t - 16;
        float2 v = make_float2(1.f, 0.f);
        #pragma unroll
        for (int i = 0; i < 4; i++){
            int bi = (s >> (3 - i)) & 1;
            v = cmul(v, sT[0][i][bi*2 + 0]);
        }
        int c0=(s>>3)&1, c1=(s>>2)&1, c2=(s>>1)&1, c3=s&1;
        int e = (c0&c1) ^ (c1&c2) ^ (c2&c3) ^ (c0&c3);
        if (e) { v.x = -v.x; v.y = -v.y; }
        sPsi0[s] = v;
    }
    __syncthreads();

    if (b0 >= B) return;

    float xq[2][4] = {{xv0.x, xv0.y, xv0.z, xv0.w},
                      {xv1.x, xv1.y, xv1.z, xv1.w}};

    ull Rr[2][8], Ii[2][8];
    #pragma unroll
    for (int m = 0; m < 8; m++){
        float2 a = sPsi0[2*m], c = sPsi0[2*m+1];
        ull pr = pk2(a.x, c.x), pi = pk2(a.y, c.y);
        Rr[0][m] = pr; Ii[0][m] = pi;
        Rr[1][m] = pr; Ii[1][m] = pi;
    }

    // ---- layers 0 and 1: full state evolution, two elements interleaved ----
    #pragma unroll
    for (int l = 0; l < 2; l++){
        float ca[2][4], sa[2][4], uP[2][2], vP[2][2];
        #pragma unroll
        for (int e = 0; e < 2; e++){
            float aa[4];
            #pragma unroll
            for (int i = 0; i < 4; i++){
                aa[i] = sL[l*4 + i] * xq[e][i];
                __sincosf(aa[i], &sa[e][i], &ca[e][i]);
            }
            #pragma unroll
            for (int p = 0; p < 2; p++){
                float chz, shz;
                __sincosf(0.5f * aa[p], &shz, &chz);
                uP[e][p] = 0.5f * (chz + shz);
                vP[e][p] = 0.5f * (chz - shz);
            }
        }
        #pragma unroll
        for (int i = 0; i < 4; i++){
            const int p = i >> 1;
            #pragma unroll
            for (int e = 0; e < 2; e++){
                float2 G00, G01;
                build_G(uP[e][p], vP[e][p], ca[e][i], sa[e][i],
                        sP[l][i][0], sP[l][i][1], G00, G01);
                apply_gate(Rr[e], Ii[e], i, G00, G01);
            }
        }
        // CZ after layers 0 and 1
        #pragma unroll
        for (int e = 0; e < 2; e++){
            Rr[e][1] ^= SGN_HI; Ii[e][1] ^= SGN_HI;
            Rr[e][3] ^= SGN_LO; Ii[e][3] ^= SGN_LO;
            Rr[e][4] ^= SGN_HI; Ii[e][4] ^= SGN_HI;
            Rr[e][6] ^= SGN_LO; Ii[e][6] ^= SGN_LO;
        }
    }

    // ---- layer 2: virtual gates -> observables; epilogue per element ----
    #pragma unroll
    for (int e = 0; e < 2; e++){
        float2 G00a[4], G01a[4];
        {
            float aa[4], ca[4], sa[4];
            #pragma unroll
            for (int i = 0; i < 4; i++){
                aa[i] = sL[8 + i] * xq[e][i];
                __sincosf(aa[i], &sa[i], &ca[i]);
            }
            float uP[2], vP[2];
            #pragma unroll
            for (int p = 0; p < 2; p++){
                float chz, shz;
                __sincosf(0.5f * aa[p], &shz, &chz);
                uP[p] = 0.5f * (chz + shz);
                vP[p] = 0.5f * (chz - shz);
            }
            #pragma unroll
            for (int i = 0; i < 4; i++)
                build_G(uP[i>>1], vP[i>>1], ca[i], sa[i],
                        sP[2][i][0], sP[2][i][1], G00a[i], G01a[i]);
        }

        float nq[4], Aq[4], Bq[4];
        #pragma unroll
        for (int i = 0; i < 4; i++){
            float g0x = G00a[i].x, g0y = G00a[i].y;
            float g1x = G01a[i].x, g1y = G01a[i].y;
            nq[i] = fmaf(g0x, g0x, g0y*g0y) - fmaf(g1x, g1x, g1y*g1y);
            Aq[i] = 4.f * fmaf(g0x, g1x,  g0y*g1y);
            Bq[i] = 4.f * fmaf(g0x, g1y, -g0y*g1x);
        }

        // norms + Walsh diffs
        float d3 = 0.f;
        float ee[8];
        #pragma unroll
        for (int m = 0; m < 8; m++){
            ull q = fma2(Ii[e][m], Ii[e][m], mul2(Rr[e][m], Rr[e][m]));
            float plo, phi; unpk(q, plo, phi);
            d3 += (plo - phi);
            ee[m] = plo + phi;
        }
        float d2 = (ee[0]-ee[1]) + (ee[2]-ee[3]) + (ee[4]-ee[5]) + (ee[6]-ee[7]);
        float f0 = ee[0]+ee[1], f1 = ee[2]+ee[3], f2 = ee[4]+ee[5], f3 = ee[6]+ee[7];
        float d1 = (f0-f1) + (f2-f3);
        float d0 = (f0 + f1) - (f2 + f3);

        // cross terms
        float Sq[4];
        #pragma unroll
        for (int q = 0; q < 3; q++){
            const int hs = 4 >> q;
            ull dA  = dup2( Aq[q]);
            ull dnB = dup2(-Bq[q]);
            ull acc = 0;
            #pragma unroll
            for (int m = 0; m < 8; m++){
                if (m & hs) continue;
                const int u0 = m, v0 = m + hs;
                ull cr2 = fma2(Ii[e][u0], Ii[e][v0], mul2(Rr[e][u0], Rr[e][v0]));
                ull ci2 = fma2(Rr[e][u0], Ii[e][v0], mul2(Ii[e][u0], Rr[e][v0]) ^ SGN_BOTH);
                acc = fma2(dA, cr2, acc);
                acc = fma2(dnB, ci2, acc);
            }
            float lo, hi; unpk(acc, lo, hi);
            Sq[q] = lo + hi;
        }
        {
            ull dAh = dup2(0.5f * Aq[3]);
            ull cB  = pk2(-Bq[3], Bq[3]);
            ull acc = 0;
            #pragma unroll
            for (int m = 0; m < 8; m++){
                ull Rs = swp(Rr[e][m]), Is = swp(Ii[e][m]);
                ull crpk = fma2(Ii[e][m], Is, mul2(Rr[e][m], Rs));
                ull cpk  = mul2(Rr[e][m], Is);
                acc = fma2(dAh, crpk, acc);
                acc = fma2(cB,  cpk,  acc);
            }
            float lo, hi; unpk(acc, lo, hi);
            Sq[3] = lo + hi;
        }

        float4 res = make_float4(fmaf(nq[0], d0, Sq[0]),
                                 fmaf(nq[1], d1, Sq[1]),
                                 fmaf(nq[2], d2, Sq[2]),
                                 fmaf(nq[3], d3, Sq[3]));
        int bb = (e == 0) ? b0 : b1;
        if (bb < B) out[bb] = res;
    }
}

extern "C" void kernel_launch(void* const* d_in, const int* in_sizes, int n_in,
                              void* d_out, int out_size)
{
    const float* x     = (const float*)d_in[0];
    const float* theta = (const float*)d_in[1];
    const float* lmbd  = (const float*)d_in[2];
    int B = in_sizes[0] / 4;

    vqc_fused<<<(B + 255) / 256, 128>>>((const float4*)x, theta, lmbd,
                                        (float4*)d_out, B);
}

// round 14
// speedup vs baseline: 1.0030x; 1.0030x over previous
#include <cuda_runtime.h>

#define DIM 16
typedef unsigned long long ull;

#define SGN_BOTH 0x8000000080000000ull
#define SGN_HI   0x8000000000000000ull
#define SGN_LO   0x0000000080000000ull

// ---------- packed f32x2 helpers ----------
__device__ __forceinline__ ull pk2(float lo, float hi){
    ull r; asm("mov.b64 %0, {%1, %2};" : "=l"(r) : "f"(lo), "f"(hi)); return r;
}
__device__ __forceinline__ ull dup2(float v){ return pk2(v, v); }
__device__ __forceinline__ ull fma2(ull a, ull b, ull c){
    ull d; asm("fma.rn.f32x2 %0, %1, %2, %3;" : "=l"(d) : "l"(a), "l"(b), "l"(c)); return d;
}
__device__ __forceinline__ ull mul2(ull a, ull b){
    ull d; asm("mul.rn.f32x2 %0, %1, %2;" : "=l"(d) : "l"(a), "l"(b)); return d;
}
__device__ __forceinline__ ull swp(ull v){
    unsigned lo, hi; asm("mov.b64 {%0, %1}, %2;" : "=r"(lo), "=r"(hi) : "l"(v));
    ull r; asm("mov.b64 %0, {%1, %2};" : "=l"(r) : "r"(hi), "r"(lo)); return r;
}
__device__ __forceinline__ void unpk(ull v, float& lo, float& hi){
    asm("mov.b64 {%0, %1}, %2;" : "=f"(lo), "=f"(hi) : "l"(v));
}

// ---------- scalar complex helpers (prologue + G build) ----------
__device__ __forceinline__ float2 cmul(float2 a, float2 b){
    return make_float2(fmaf(a.x, b.x, -a.y * b.y),
                       fmaf(a.x, b.y,  a.y * b.x));
}
__device__ __forceinline__ float2 cmadd(float2 a, float2 b, float2 acc){
    acc.x = fmaf(a.x, b.x, fmaf(-a.y, b.y, acc.x));
    acc.y = fmaf(a.x, b.y, fmaf( a.y, b.x, acc.y));
    return acc;
}
__device__ __forceinline__ void mm2(const float2* A, const float2* B, float2* C){
    C[0] = cmadd(A[1], B[2], cmul(A[0], B[0]));
    C[1] = cmadd(A[1], B[3], cmul(A[0], B[1]));
    C[2] = cmadd(A[3], B[2], cmul(A[2], B[0]));
    C[3] = cmadd(A[3], B[3], cmul(A[2], B[1]));
}

// build gate G = P * Rz(z)Ry(a)Rx(a) top row from (u,v,ca,sa)
__device__ __forceinline__ void build_G(float u, float v, float ca, float sa,
                                        float2 P00, float2 P01,
                                        float2& G00, float2& G01)
{
    float2 M00 = make_float2(fmaf(ca, v, u), fmaf(-ca, u, v));
    float2 M01 = make_float2(-sa * u, -sa * v);
    float2 M10 = make_float2(-M01.x,  M01.y);
    float2 M11 = make_float2( M00.x, -M00.y);
    G00 = cmadd(P01, M10, cmul(P00, M00));
    G01 = cmadd(P01, M11, cmul(P00, M01));
}

__global__ void __launch_bounds__(128, 8) vqc_fused(
    const float4* __restrict__ x, const float* __restrict__ theta,
    const float* __restrict__ lmbd, float4* __restrict__ out, int B)
{
    __shared__ float2 sT[4][4][4];
    __shared__ float2 sP[3][4][2];
    __shared__ float2 sPsi0[DIM];
    __shared__ float  sL[12];

    const int t = threadIdx.x;
    const int b = blockIdx.x * blockDim.x + t;

    // hoisted input load: overlap DRAM latency with prologue + barriers
    float4 xv = make_float4(0.f, 0.f, 0.f, 0.f);
    if (b < B) xv = x[b];

    // ---- prologue stage 1 ----
    if (t < 16){
        int l = t >> 2, i = t & 3;
        float t0 = theta[t*3 + 0], t1 = theta[t*3 + 1], t2 = theta[t*3 + 2];
        float cx, sx, cy, sy, cz, sz;
        __sincosf(0.5f*t0, &sx, &cx);
        __sincosf(0.5f*t1, &sy, &cy);
        __sincosf(0.5f*t2, &sz, &cz);
        float2 RX[4] = {{cx,0.f},{0.f,-sx},{0.f,-sx},{cx,0.f}};
        float2 RY[4] = {{cy,0.f},{-sy,0.f},{sy,0.f},{cy,0.f}};
        float2 RZ[4] = {{cz,-sz},{0.f,0.f},{0.f,0.f},{cz,sz}};
        float2 YX[4], M[4];
        mm2(RY, RX, YX);
        mm2(RZ, YX, M);
        #pragma unroll
        for (int e = 0; e < 4; e++) sT[l][i][e] = M[e];
    }
    if (t >= 32 && t < 44) sL[t - 32] = lmbd[t - 32];
    __syncthreads();

    // ---- prologue stage 2 ----
    if (t < 12){
        int l = t >> 2, i = t & 3;
        float2 G0, G1;
        if (l < 2){
            G0 = cmadd(sT[l+1][i][1], sT[3][i][2], cmul(sT[l+1][i][0], sT[3][i][0]));
            G1 = cmadd(sT[l+1][i][1], sT[3][i][3], cmul(sT[l+1][i][0], sT[3][i][1]));
        } else {
            G0 = sT[3][i][0];
            G1 = sT[3][i][1];
        }
        sP[l][i][0] = G0;
        sP[l][i][1] = G1;
    }
    if (t >= 16 && t < 32){
        int s = t - 16;
        float2 v = make_float2(1.f, 0.f);
        #pragma unroll
        for (int i = 0; i < 4; i++){
            int bi = (s >> (3 - i)) & 1;
            v = cmul(v, sT[0][i][bi*2 + 0]);
        }
        int c0=(s>>3)&1, c1=(s>>2)&1, c2=(s>>1)&1, c3=s&1;
        int e = (c0&c1) ^ (c1&c2) ^ (c2&c3) ^ (c0&c3);
        if (e) { v.x = -v.x; v.y = -v.y; }
        sPsi0[s] = v;
    }
    __syncthreads();

    // ---- main per-element circuit ----
    if (b >= B) return;

    float xq[4] = {xv.x, xv.y, xv.z, xv.w};

    ull Rr[8], Ii[8];
    #pragma unroll
    for (int m = 0; m < 8; m++){
        float2 a = sPsi0[2*m], c = sPsi0[2*m+1];
        Rr[m] = pk2(a.x, c.x);
        Ii[m] = pk2(a.y, c.y);
    }

    // ---- layers 0 and 1: ROLLED loop (identical body; shrink I$ footprint) ----
    #pragma unroll 1
    for (int l = 0; l < 2; l++){
        float aa[4], ca[4], sa[4];
        #pragma unroll
        for (int i = 0; i < 4; i++){
            aa[i] = sL[l*4 + i] * xq[i];
            __sincosf(aa[i], &sa[i], &ca[i]);
        }
        float uP[2], vP[2];
        #pragma unroll
        for (int p = 0; p < 2; p++){
            float chz, shz;
            __sincosf(0.5f * aa[p], &shz, &chz);
            uP[p] = 0.5f * (chz + shz);
            vP[p] = 0.5f * (chz - shz);
        }
        #pragma unroll
        for (int i = 0; i < 4; i++){
            const int p = i >> 1;
            float2 G00, G01;
            build_G(uP[p], vP[p], ca[i], sa[i], sP[l][i][0], sP[l][i][1], G00, G01);

            if (i < 3){
                ull pG00x  = dup2(G00.x), pG00y  = dup2(G00.y);
                ull pG01x  = dup2(G01.x), pG01y  = dup2(G01.y);
                ull pnG00y = pG00y ^ SGN_BOTH;
                ull pnG01x = pG01x ^ SGN_BOTH;
                ull pnG01y = pG01y ^ SGN_BOTH;
                const int hs = 4 >> i;
                #pragma unroll
                for (int m = 0; m < 8; m++){
                    if (m & hs) continue;
                    const int u0 = m, v0 = m + hs;
                    ull R0 = Rr[u0], I0 = Ii[u0], R1 = Rr[v0], I1 = Ii[v0];
                    Rr[u0] = fma2(pnG01y,I1, fma2(pG01x ,R1, fma2(pnG00y,I0, mul2(pG00x ,R0))));
                    Ii[u0] = fma2(pG01x ,I1, fma2(pG01y ,R1, fma2(pG00x ,I0, mul2(pG00y ,R0))));
                    Rr[v0] = fma2(pG00y ,I1, fma2(pG00x ,R1, fma2(pnG01y,I0, mul2(pnG01x,R0))));
                    Ii[v0] = fma2(pG00x ,I1, fma2(pnG00y,R1, fma2(pnG01x,I0, mul2(pG01y ,R0))));
                }
            } else {
                ull c1  = dup2(G00.x);
                ull c6  = dup2(G01.y);
                ull c2v = dup2(G01.x) ^ SGN_HI;
                ull c3  = dup2(G00.y) ^ SGN_LO;
                ull c4  = c6 ^ SGN_BOTH;
                ull c5  = dup2(G00.y) ^ SGN_HI;
                #pragma unroll
                for (int m = 0; m < 8; m++){
                    ull R = Rr[m], I = Ii[m];
                    ull Rs = swp(R), Is = swp(I);
                    Rr[m] = fma2(c4, Is, fma2(c3, I, fma2(c2v, Rs, mul2(c1, R))));
                    Ii[m] = fma2(c6, Rs, fma2(c5, R, fma2(c2v, Is, mul2(c1, I))));
                }
            }
        }
        // CZ after layers 0 and 1 (both iterations)
        Rr[1] ^= SGN_HI; Ii[1] ^= SGN_HI;
        Rr[3] ^= SGN_LO; Ii[3] ^= SGN_LO;
        Rr[4] ^= SGN_HI; Ii[4] ^= SGN_HI;
        Rr[6] ^= SGN_LO; Ii[6] ^= SGN_LO;
    }

    // ---- layer 2: virtual gates -> observables ----
    float2 G00a[4], G01a[4];
    {
        float aa[4], ca[4], sa[4];
        #pragma unroll
        for (int i = 0; i < 4; i++){
            aa[i] = sL[8 + i] * xq[i];
            __sincosf(aa[i], &sa[i], &ca[i]);
        }
        float uP[2], vP[2];
        #pragma unroll
        for (int p = 0; p < 2; p++){
            float chz, shz;
            __sincosf(0.5f * aa[p], &shz, &chz);
            uP[p] = 0.5f * (chz + shz);
            vP[p] = 0.5f * (chz - shz);
        }
        #pragma unroll
        for (int i = 0; i < 4; i++)
            build_G(uP[i>>1], vP[i>>1], ca[i], sa[i],
                    sP[2][i][0], sP[2][i][1], G00a[i], G01a[i]);
    }

    float nq[4], Aq[4], Bq[4];
    #pragma unroll
    for (int i = 0; i < 4; i++){
        float g0x = G00a[i].x, g0y = G00a[i].y;
        float g1x = G01a[i].x, g1y = G01a[i].y;
        nq[i] = fmaf(g0x, g0x, g0y*g0y) - fmaf(g1x, g1x, g1y*g1y);
        Aq[i] = 4.f * fmaf(g0x, g1x,  g0y*g1y);
        Bq[i] = 4.f * fmaf(g0x, g1y, -g0y*g1x);
    }

    // norms + Walsh diffs
    float d3 = 0.f;
    float e[8];
    #pragma unroll
    for (int m = 0; m < 8; m++){
        ull q = fma2(Ii[m], Ii[m], mul2(Rr[m], Rr[m]));
        float plo, phi; unpk(q, plo, phi);
        d3 += (plo - phi);
        e[m] = plo + phi;
    }
    float d2 = (e[0]-e[1]) + (e[2]-e[3]) + (e[4]-e[5]) + (e[6]-e[7]);
    float f0 = e[0]+e[1], f1 = e[2]+e[3], f2 = e[4]+e[5], f3 = e[6]+e[7];
    float d1 = (f0-f1) + (f2-f3);
    float d0 = (f0 + f1) - (f2 + f3);

    // cross terms
    float Sq[4];
    #pragma unroll
    for (int q = 0; q < 3; q++){
        const int hs = 4 >> q;
        ull dA  = dup2( Aq[q]);
        ull dnB = dup2(-Bq[q]);
        ull acc = 0;
        #pragma unroll
        for (int m = 0; m < 8; m++){
            if (m & hs) continue;
            const int u0 = m, v0 = m + hs;
            ull cr2 = fma2(Ii[u0], Ii[v0], mul2(Rr[u0], Rr[v0]));
            ull ci2 = fma2(Rr[u0], Ii[v0], mul2(Ii[u0], Rr[v0]) ^ SGN_BOTH);
            acc = fma2(dA, cr2, acc);
            acc = fma2(dnB, ci2, acc);
        }
        float lo, hi; unpk(acc, lo, hi);
        Sq[q] = lo + hi;
    }
    {
        ull dAh = dup2(0.5f * Aq[3]);
        ull cB  = pk2(-Bq[3], Bq[3]);
        ull acc = 0;
        #pragma unroll
        for (int m = 0; m < 8; m++){
            ull Rs = swp(Rr[m]), Is = swp(Ii[m]);
            ull crpk = fma2(Ii[m], Is, mul2(Rr[m], Rs));
            ull cpk  = mul2(Rr[m], Is);
            acc = fma2(dAh, crpk, acc);
            acc = fma2(cB,  cpk,  acc);
        }
        float lo, hi; unpk(acc, lo, hi);
        Sq[3] = lo + hi;
    }

    out[b] = make_float4(fmaf(nq[0], d0, Sq[0]),
                         fmaf(nq[1], d1, Sq[1]),
                         fmaf(nq[2], d2, Sq[2]),
                         fmaf(nq[3], d3, Sq[3]));
}

extern "C" void kernel_launch(void* const* d_in, const int* in_sizes, int n_in,
                              void* d_out, int out_size)
{
    const float* x     = (const float*)d_in[0];
    const float* theta = (const float*)d_in[1];
    const float* lmbd  = (const float*)d_in[2];
    int B = in_sizes[0] / 4;

    vqc_fused<<<(B + 127) / 128, 128>>>((const float4*)x, theta, lmbd,
                                        (float4*)d_out, B);
}

// round 15
// speedup vs baseline: 1.0137x; 1.0107x over previous
#include <cuda_runtime.h>

#define DIM 16
typedef unsigned long long ull;

#define SGN_BOTH 0x8000000080000000ull
#define SGN_HI   0x8000000000000000ull
#define SGN_LO   0x0000000080000000ull

// ---------- packed f32x2 helpers ----------
__device__ __forceinline__ ull pk2(float lo, float hi){
    ull r; asm("mov.b64 %0, {%1, %2};" : "=l"(r) : "f"(lo), "f"(hi)); return r;
}
__device__ __forceinline__ ull dup2(float v){ return pk2(v, v); }
__device__ __forceinline__ ull fma2(ull a, ull b, ull c){
    ull d; asm("fma.rn.f32x2 %0, %1, %2, %3;" : "=l"(d) : "l"(a), "l"(b), "l"(c)); return d;
}
__device__ __forceinline__ ull mul2(ull a, ull b){
    ull d; asm("mul.rn.f32x2 %0, %1, %2;" : "=l"(d) : "l"(a), "l"(b)); return d;
}
__device__ __forceinline__ ull swp(ull v){
    unsigned lo, hi; asm("mov.b64 {%0, %1}, %2;" : "=r"(lo), "=r"(hi) : "l"(v));
    ull r; asm("mov.b64 %0, {%1, %2};" : "=l"(r) : "r"(hi), "r"(lo)); return r;
}
__device__ __forceinline__ void unpk(ull v, float& lo, float& hi){
    asm("mov.b64 {%0, %1}, %2;" : "=f"(lo), "=f"(hi) : "l"(v));
}

// ---------- scalar complex helpers (prologue + G build) ----------
__device__ __forceinline__ float2 cmul(float2 a, float2 b){
    return make_float2(fmaf(a.x, b.x, -a.y * b.y),
                       fmaf(a.x, b.y,  a.y * b.x));
}
__device__ __forceinline__ float2 cmadd(float2 a, float2 b, float2 acc){
    acc.x = fmaf(a.x, b.x, fmaf(-a.y, b.y, acc.x));
    acc.y = fmaf(a.x, b.y, fmaf( a.y, b.x, acc.y));
    return acc;
}
__device__ __forceinline__ void mm2(const float2* A, const float2* B, float2* C){
    C[0] = cmadd(A[1], B[2], cmul(A[0], B[0]));
    C[1] = cmadd(A[1], B[3], cmul(A[0], B[1]));
    C[2] = cmadd(A[3], B[2], cmul(A[2], B[0]));
    C[3] = cmadd(A[3], B[3], cmul(A[2], B[1]));
}

// build gate G = P * Rz(z)Ry(a)Rx(a) top row from (u,v,ca,sa)
__device__ __forceinline__ void build_G(float u, float v, float ca, float sa,
                                        float2 P00, float2 P01,
                                        float2& G00, float2& G01)
{
    float2 M00 = make_float2(fmaf(ca, v, u), fmaf(-ca, u, v));
    float2 M01 = make_float2(-sa * u, -sa * v);
    float2 M10 = make_float2(-M01.x,  M01.y);
    float2 M11 = make_float2( M00.x, -M00.y);
    G00 = cmadd(P01, M10, cmul(P00, M00));
    G01 = cmadd(P01, M11, cmul(P00, M01));
}

__global__ void __launch_bounds__(128, 8) vqc_fused(
    const float4* __restrict__ x, const float* __restrict__ theta,
    const float* __restrict__ lmbd, float4* __restrict__ out, int B)
{
    __shared__ float2 sT[4][4][4];
    __shared__ float2 sP[3][4][2];
    __shared__ float2 sPsi0[DIM];
    __shared__ float  sL[12];

    const int t = threadIdx.x;
    const int b = blockIdx.x * blockDim.x + t;

    // hoisted input load: overlap DRAM latency with prologue + barriers
    float4 xv = make_float4(0.f, 0.f, 0.f, 0.f);
    if (b < B) xv = x[b];

    // ---- prologue stage 1 ----
    if (t < 16){
        int l = t >> 2, i = t & 3;
        float t0 = theta[t*3 + 0], t1 = theta[t*3 + 1], t2 = theta[t*3 + 2];
        float cx, sx, cy, sy, cz, sz;
        __sincosf(0.5f*t0, &sx, &cx);
        __sincosf(0.5f*t1, &sy, &cy);
        __sincosf(0.5f*t2, &sz, &cz);
        float2 RX[4] = {{cx,0.f},{0.f,-sx},{0.f,-sx},{cx,0.f}};
        float2 RY[4] = {{cy,0.f},{-sy,0.f},{sy,0.f},{cy,0.f}};
        float2 RZ[4] = {{cz,-sz},{0.f,0.f},{0.f,0.f},{cz,sz}};
        float2 YX[4], M[4];
        mm2(RY, RX, YX);
        mm2(RZ, YX, M);
        #pragma unroll
        for (int e = 0; e < 4; e++) sT[l][i][e] = M[e];
    }
    if (t >= 32 && t < 44) sL[t - 32] = lmbd[t - 32];
    __syncthreads();

    // ---- prologue stage 2 ----
    if (t < 12){
        int l = t >> 2, i = t & 3;
        float2 G0, G1;
        if (l < 2){
            G0 = cmadd(sT[l+1][i][1], sT[3][i][2], cmul(sT[l+1][i][0], sT[3][i][0]));
            G1 = cmadd(sT[l+1][i][1], sT[3][i][3], cmul(sT[l+1][i][0], sT[3][i][1]));
        } else {
            G0 = sT[3][i][0];
            G1 = sT[3][i][1];
        }
        sP[l][i][0] = G0;
        sP[l][i][1] = G1;
    }
    if (t >= 16 && t < 32){
        int s = t - 16;
        float2 v = make_float2(1.f, 0.f);
        #pragma unroll
        for (int i = 0; i < 4; i++){
            int bi = (s >> (3 - i)) & 1;
            v = cmul(v, sT[0][i][bi*2 + 0]);
        }
        int c0=(s>>3)&1, c1=(s>>2)&1, c2=(s>>1)&1, c3=s&1;
        int e = (c0&c1) ^ (c1&c2) ^ (c2&c3) ^ (c0&c3);
        if (e) { v.x = -v.x; v.y = -v.y; }
        sPsi0[s] = v;
    }
    __syncthreads();

    // ---- main per-element circuit ----
    if (b >= B) return;

    float xq[4] = {xv.x, xv.y, xv.z, xv.w};

    ull Rr[8], Ii[8];
    #pragma unroll
    for (int m = 0; m < 8; m++){
        float2 a = sPsi0[2*m], c = sPsi0[2*m+1];
        Rr[m] = pk2(a.x, c.x);
        Ii[m] = pk2(a.y, c.y);
    }

    // ---- layers 0 and 1: full state evolution (fully unrolled, proven R12) ----
    #pragma unroll
    for (int l = 0; l < 2; l++){
        float aa[4], ca[4], sa[4];
        #pragma unroll
        for (int i = 0; i < 4; i++){
            aa[i] = sL[l*4 + i] * xq[i];
            __sincosf(aa[i], &sa[i], &ca[i]);
        }
        float uP[2], vP[2];
        #pragma unroll
        for (int p = 0; p < 2; p++){
            float chz, shz;
            __sincosf(0.5f * aa[p], &shz, &chz);
            uP[p] = 0.5f * (chz + shz);
            vP[p] = 0.5f * (chz - shz);
        }
        #pragma unroll
        for (int i = 0; i < 4; i++){
            const int p = i >> 1;
            float2 G00, G01;
            build_G(uP[p], vP[p], ca[i], sa[i], sP[l][i][0], sP[l][i][1], G00, G01);

            if (i < 3){
                ull pG00x  = dup2(G00.x), pG00y  = dup2(G00.y);
                ull pG01x  = dup2(G01.x), pG01y  = dup2(G01.y);
                ull pnG00y = pG00y ^ SGN_BOTH;
                ull pnG01x = pG01x ^ SGN_BOTH;
                ull pnG01y = pG01y ^ SGN_BOTH;
                const int hs = 4 >> i;
                #pragma unroll
                for (int m = 0; m < 8; m++){
                    if (m & hs) continue;
                    const int u0 = m, v0 = m + hs;
                    ull R0 = Rr[u0], I0 = Ii[u0], R1 = Rr[v0], I1 = Ii[v0];
                    Rr[u0] = fma2(pnG01y,I1, fma2(pG01x ,R1, fma2(pnG00y,I0, mul2(pG00x ,R0))));
                    Ii[u0] = fma2(pG01x ,I1, fma2(pG01y ,R1, fma2(pG00x ,I0, mul2(pG00y ,R0))));
                    Rr[v0] = fma2(pG00y ,I1, fma2(pG00x ,R1, fma2(pnG01y,I0, mul2(pnG01x,R0))));
                    Ii[v0] = fma2(pG00x ,I1, fma2(pnG00y,R1, fma2(pnG01x,I0, mul2(pG01y ,R0))));
                }
            } else {
                ull c1  = dup2(G00.x);
                ull c6  = dup2(G01.y);
                ull c2v = dup2(G01.x) ^ SGN_HI;
                ull c3  = dup2(G00.y) ^ SGN_LO;
                ull c4  = c6 ^ SGN_BOTH;
                ull c5  = dup2(G00.y) ^ SGN_HI;
                #pragma unroll
                for (int m = 0; m < 8; m++){
                    ull R = Rr[m], I = Ii[m];
                    ull Rs = swp(R), Is = swp(I);
                    Rr[m] = fma2(c4, Is, fma2(c3, I, fma2(c2v, Rs, mul2(c1, R))));
                    Ii[m] = fma2(c6, Rs, fma2(c5, R, fma2(c2v, Is, mul2(c1, I))));
                }
            }
        }
        // CZ after layers 0 and 1
        Rr[1] ^= SGN_HI; Ii[1] ^= SGN_HI;
        Rr[3] ^= SGN_LO; Ii[3] ^= SGN_LO;
        Rr[4] ^= SGN_HI; Ii[4] ^= SGN_HI;
        Rr[6] ^= SGN_LO; Ii[6] ^= SGN_LO;
    }

    // ---- layer 2: virtual gates -> observables ----
    float2 G00a[4], G01a[4];
    {
        float aa[4], ca[4], sa[4];
        #pragma unroll
        for (int i = 0; i < 4; i++){
            aa[i] = sL[8 + i] * xq[i];
            __sincosf(aa[i], &sa[i], &ca[i]);
        }
        float uP[2], vP[2];
        #pragma unroll
        for (int p = 0; p < 2; p++){
            float chz, shz;
            __sincosf(0.5f * aa[p], &shz, &chz);
            uP[p] = 0.5f * (chz + shz);
            vP[p] = 0.5f * (chz - shz);
        }
        #pragma unroll
        for (int i = 0; i < 4; i++)
            build_G(uP[i>>1], vP[i>>1], ca[i], sa[i],
                    sP[2][i][0], sP[2][i][1], G00a[i], G01a[i]);
    }

    float nq[4], Aq[4], Bq[4];
    #pragma unroll
    for (int i = 0; i < 4; i++){
        float g0x = G00a[i].x, g0y = G00a[i].y;
        float g1x = G01a[i].x, g1y = G01a[i].y;
        nq[i] = fmaf(g0x, g0x, g0y*g0y) - fmaf(g1x, g1x, g1y*g1y);
        Aq[i] = 4.f * fmaf(g0x, g1x,  g0y*g1y);
        Bq[i] = 4.f * fmaf(g0x, g1y, -g0y*g1x);
    }

    // norms + Walsh diffs
    float d3 = 0.f;
    float e[8];
    #pragma unroll
    for (int m = 0; m < 8; m++){
        ull q = fma2(Ii[m], Ii[m], mul2(Rr[m], Rr[m]));
        float plo, phi; unpk(q, plo, phi);
        d3 += (plo - phi);
        e[m] = plo + phi;
    }
    float d2 = (e[0]-e[1]) + (e[2]-e[3]) + (e[4]-e[5]) + (e[6]-e[7]);
    float f0 = e[0]+e[1], f1 = e[2]+e[3], f2 = e[4]+e[5], f3 = e[6]+e[7];
    float d1 = (f0-f1) + (f2-f3);
    float d0 = (f0 + f1) - (f2 + f3);

    // cross terms: DEFERRED A/B application — accumulate raw CR/CI, scale once
    float Sq[4];
    #pragma unroll
    for (int q = 0; q < 3; q++){
        const int hs = 4 >> q;
        ull CR = 0, CI = 0;
        #pragma unroll
        for (int m = 0; m < 8; m++){
            if (m & hs) continue;
            const int u0 = m, v0 = m + hs;
            CR = fma2(Rr[u0], Rr[v0], CR);               // += R0*R1
            CR = fma2(Ii[u0], Ii[v0], CR);               // += I0*I1
            CI = fma2(Rr[u0], Ii[v0], CI);               // += R0*I1
            CI = fma2(Ii[u0] ^ SGN_BOTH, Rr[v0], CI);    // -= I0*R1
        }
        float crlo, crhi, cilo, cihi;
        unpk(CR, crlo, crhi);
        unpk(CI, cilo, cihi);
        Sq[q] = fmaf(Aq[q], crlo + crhi, -Bq[q] * (cilo + cihi));
    }
    {   // qubit 3: pairs within packed registers
        ull CR = 0, CP = 0;
        #pragma unroll
        for (int m = 0; m < 8; m++){
            ull Rs = swp(Rr[m]), Is = swp(Ii[m]);
            CR = fma2(Rr[m], Rs, CR);    // both lanes: Rlo*Rhi (+ Ilo*Ihi below)
            CR = fma2(Ii[m], Is, CR);
            CP = fma2(Rr[m], Is, CP);    // lo: Rlo*Ihi ; hi: Rhi*Ilo
        }
        float crlo, crhi, cplo, cphi;
        unpk(CR, crlo, crhi);            // crlo+crhi = 2*sum(cr)
        unpk(CP, cplo, cphi);            // sum(ci) = cplo - cphi
        Sq[3] = fmaf(0.5f * Aq[3], crlo + crhi, -Bq[3] * (cplo - cphi));
    }

    out[b] = make_float4(fmaf(nq[0], d0, Sq[0]),
                         fmaf(nq[1], d1, Sq[1]),
                         fmaf(nq[2], d2, Sq[2]),
                         fmaf(nq[3], d3, Sq[3]));
}

extern "C" void kernel_launch(void* const* d_in, const int* in_sizes, int n_in,
                              void* d_out, int out_size)
{
    const float* x     = (const float*)d_in[0];
    const float* theta = (const float*)d_in[1];
    const float* lmbd  = (const float*)d_in[2];
    int B = in_sizes[0] / 4;

    vqc_fused<<<(B + 127) / 128, 128>>>((const float4*)x, theta, lmbd,
                                        (float4*)d_out, B);
}